// round 2
// baseline (speedup 1.0000x reference)
#include <cuda_runtime.h>

#define NB   4
#define CIN  256
#define CO   128
#define HIN  64
#define HH   128

typedef unsigned long long u64;

// ---- packed fp32x2 helpers (sm_100+ dual-rate fp32) ----
__device__ __forceinline__ u64 pk2(float lo, float hi) {
    u64 r;
    asm("mov.b64 %0, {%1, %2};" : "=l"(r)
        : "r"(__float_as_uint(lo)), "r"(__float_as_uint(hi)));
    return r;
}
__device__ __forceinline__ void unpk2(u64 v, float& lo, float& hi) {
    unsigned int a, b;
    asm("mov.b64 {%0, %1}, %2;" : "=r"(a), "=r"(b) : "l"(v));
    lo = __uint_as_float(a); hi = __uint_as_float(b);
}
__device__ __forceinline__ u64 fma2(u64 a, u64 b, u64 c) {
    u64 d;
    asm("fma.rn.f32x2 %0, %1, %2, %3;" : "=l"(d) : "l"(a), "l"(b), "l"(c));
    return d;
}
__device__ __forceinline__ u64 mul2(u64 a, u64 b) {
    u64 d;
    asm("mul.rn.f32x2 %0, %1, %2;" : "=l"(d) : "l"(a), "l"(b));
    return d;
}

// Scratch (device globals: allocation is banned)
__device__ float g_y[(size_t)NB * CO * HH * HH];   // stage-1 output, NCHW
__device__ float g_k[(size_t)NB * 9 * HH * HH];    // PAC gaussian weights [b][tap][h][w]

// ---------------------------------------------------------------------------
// Stage 1: ConvTranspose2d(256->128, k=4, s=2, p=1) as 4 parity classes.
// Class (p,q): out(2a+p, 2bb+q) is a 2x2 conv over x. Block = (b,p,a);
// 256 threads, each owns 16(co) x 2(bb). Packed f32x2 over the bb pair;
// weights stored DUPLICATED in smem so one LDS.128 feeds two FFMA2s.
// ---------------------------------------------------------------------------
template <int Q>
__global__ __launch_bounds__(256, 2) void stage1_kernel(
    const float* __restrict__ x, const float* __restrict__ w1,
    const float* __restrict__ b1)
{
    const int a   = blockIdx.x;          // 0..63
    const int p   = blockIdx.y;          // 0..1
    const int b   = blockIdx.z;          // 0..3
    const int tid = threadIdx.x;
    const int to  = tid >> 5;            // 0..7  -> co base = to*16
    const int tw  = tid & 31;            // bb pair = 2*tw, 2*tw+1

    const int khb = p ? 0 : 1;
    const int kwb = Q ? 0 : 1;
    const int r0  = a + (p ? 1 : 0);     // x row for s=0; s=1 uses r0-1

    __shared__ u64   wsm[8][128][4];     // dup pairs, taps (s,t): (0,0)(0,1)(1,0)(1,1)
    __shared__ float xsm[8][2][68];      // [ci][s][iw+1], padded row

    u64 acc[16];
#pragma unroll
    for (int i = 0; i < 16; i++) acc[i] = 0ull;

    const float* xb = x + (size_t)b * CIN * HIN * HIN;
    const int lci  = tid >> 5;           // ci this thread fills in x slab
    const int lane = tid & 31;

    for (int c0 = 0; c0 < CIN; c0 += 8) {
        __syncthreads();
        // weights: 8 ci x 128 co, 4 taps each, duplicated lanes (shift/mask only)
#pragma unroll 4
        for (int i = tid; i < 8 * 128; i += 256) {
            int ci = i >> 7, co = i & 127;
            const float* wp = w1 + ((size_t)(c0 + ci) * CO + co) * 16;
            float v0 = __ldg(wp + khb * 4 + kwb);
            float v1 = __ldg(wp + khb * 4 + kwb + 2);
            float v2 = __ldg(wp + (khb + 2) * 4 + kwb);
            float v3 = __ldg(wp + (khb + 2) * 4 + kwb + 2);
            wsm[ci][co][0] = pk2(v0, v0);
            wsm[ci][co][1] = pk2(v1, v1);
            wsm[ci][co][2] = pk2(v2, v2);
            wsm[ci][co][3] = pk2(v3, v3);
        }
        // x slab: thread group (32 lanes) per ci, no div/mod
#pragma unroll
        for (int s = 0; s < 2; s++) {
            int ih = r0 - s;
            bool hv = (unsigned)ih < (unsigned)HIN;
            const float* xr = xb + ((size_t)(c0 + lci) * HIN + (hv ? ih : 0)) * HIN;
#pragma unroll
            for (int col = lane; col < 66; col += 32) {
                int iw = col - 1;
                float v = 0.f;
                if (hv && (unsigned)iw < (unsigned)HIN) v = __ldg(xr + iw);
                xsm[lci][s][col] = v;
            }
        }
        __syncthreads();

#pragma unroll
        for (int ci = 0; ci < 8; ci++) {
            float2 A0 = *(const float2*)&xsm[ci][0][2 * tw];
            float2 B0 = *(const float2*)&xsm[ci][0][2 * tw + 2];
            float2 A1 = *(const float2*)&xsm[ci][1][2 * tw];
            float2 B1 = *(const float2*)&xsm[ci][1][2 * tw + 2];
            u64 PA0, PB0, PA1, PB1;   // PA=(xv[M0],xv[M0+1]) PB=(xv[M0-1],xv[M0])
            if (Q) {                  // M0 = 2
                PA0 = pk2(B0.x, B0.y); PB0 = pk2(A0.y, B0.x);
                PA1 = pk2(B1.x, B1.y); PB1 = pk2(A1.y, B1.x);
            } else {                  // M0 = 1
                PA0 = pk2(A0.y, B0.x); PB0 = pk2(A0.x, A0.y);
                PA1 = pk2(A1.y, B1.x); PB1 = pk2(A1.x, A1.y);
            }
#pragma unroll
            for (int oi = 0; oi < 16; oi++) {
                const u64* wp = &wsm[ci][to * 16 + oi][0];
                ulonglong2 wa = *(const ulonglong2*)(wp + 0);
                ulonglong2 wb = *(const ulonglong2*)(wp + 2);
                u64 s_ = acc[oi];
                s_ = fma2(wa.x, PA0, s_);
                s_ = fma2(wa.y, PB0, s_);
                s_ = fma2(wb.x, PA1, s_);
                s_ = fma2(wb.y, PB1, s_);
                acc[oi] = s_;
            }
        }
    }

    const int oh = 2 * a + p;
#pragma unroll
    for (int oi = 0; oi < 16; oi++) {
        int co = to * 16 + oi;
        float bias = __ldg(b1 + co);
        float e0, e1; unpk2(acc[oi], e0, e1);
        size_t base = (((size_t)b * CO + co) * HH + oh) * HH;
        g_y[base + 4 * tw + Q]     = e0 + bias;
        g_y[base + 4 * tw + 2 + Q] = e1 + bias;
    }
}

// ---------------------------------------------------------------------------
// Stage 2a: PAC gaussian kernel map (unchanged; ~30us, not the bottleneck)
// ---------------------------------------------------------------------------
__global__ __launch_bounds__(256) void kmap_kernel(const float* __restrict__ guide)
{
    const int b  = blockIdx.z;
    const int h0 = blockIdx.y * 16, w0 = blockIdx.x * 16;
    const int tx = threadIdx.x & 15, ty = threadIdx.x >> 4;

    __shared__ float sm[18][18];
    float acc[9];
#pragma unroll
    for (int t = 0; t < 9; t++) acc[t] = 0.f;

    for (int c = 0; c < CO; c++) {
        __syncthreads();
        for (int i = threadIdx.x; i < 18 * 18; i += 256) {
            int r = i / 18, col = i % 18;
            int h = h0 + r - 1, w = w0 + col - 1;
            float v = 0.f;
            if ((unsigned)h < (unsigned)HH && (unsigned)w < (unsigned)HH)
                v = __ldg(guide + (((size_t)b * CO + c) * HH + h) * HH + w);
            sm[r][col] = v;
        }
        __syncthreads();
        float g0 = sm[ty + 1][tx + 1];
#pragma unroll
        for (int i3 = 0; i3 < 3; i3++)
#pragma unroll
            for (int j3 = 0; j3 < 3; j3++) {
                float d = sm[ty + i3][tx + j3] - g0;
                acc[i3 * 3 + j3] = fmaf(d, d, acc[i3 * 3 + j3]);
            }
    }

    int h = h0 + ty, w = w0 + tx;
#pragma unroll
    for (int t = 0; t < 9; t++)
        g_k[(((size_t)b * 9 + t) * HH + h) * HH + w] = __expf(-0.5f * acc[t]);
}

// ---------------------------------------------------------------------------
// Stage 2b: PAC transposed conv. wk[o,c,t] = w2[c,o,8-t].
// Block = (b, h, 64-px strip); 256 threads, 16(o) x 2(px) micro-tile.
// Packed f32x2 over the px pair; weights duplicated in smem (LDS.128 pairs),
// per-pixel gaussian taps packed once into registers.
// ---------------------------------------------------------------------------
__global__ __launch_bounds__(256, 2) void stage2_kernel(
    const float* __restrict__ w2, const float* __restrict__ b2,
    float* __restrict__ out)
{
    const int wstart = blockIdx.x * 64;
    const int h      = blockIdx.y;
    const int b      = blockIdx.z;
    const int tid    = threadIdx.x;
    const int to     = tid >> 5;         // 0..7 -> o base = to*16
    const int tw     = tid & 31;         // px pair = wstart + 2*tw + {0,1}
    const int w      = wstart + 2 * tw;

    __shared__ u64   wsm[4][128][10];    // dup pairs, 9 taps + pad (80B stride)
    __shared__ float ysm[4][3][68];      // padded rows

    u64 kp[9];
#pragma unroll
    for (int t = 0; t < 9; t++) {
        size_t kb = (((size_t)b * 9 + t) * HH + h) * HH + w;
        kp[t] = pk2(g_k[kb], g_k[kb + 1]);
    }

    u64 acc[16];
#pragma unroll
    for (int i = 0; i < 16; i++) acc[i] = 0ull;

    const int lo_o   = tid & 127;        // weight-fill: o index
    const int lo_c2  = (tid >> 7) * 2;   // weight-fill: c pair base
    const int yc     = tid >> 6;         // y-fill: c index (0..3)
    const int yr     = tid & 63;         // y-fill: lane within c

    for (int c0 = 0; c0 < CO; c0 += 4) {
        __syncthreads();
        // weights (flip folded): wsm[c][o][t] = dup(w2[(c0+c)*CO*9 + o*9 + 8-t])
#pragma unroll
        for (int cc = 0; cc < 2; cc++) {
            int c = lo_c2 + cc;
            const float* wp = w2 + ((size_t)(c0 + c) * CO + lo_o) * 9;
#pragma unroll
            for (int t = 0; t < 9; t++) {
                float v = __ldg(wp + 8 - t);
                wsm[c][lo_o][t] = pk2(v, v);
            }
        }
        // y slab: 4c x 3 rows x 66 cols (no div/mod)
#pragma unroll
        for (int i3 = 0; i3 < 3; i3++) {
            int hh = h + i3 - 1;
            bool hv = (unsigned)hh < (unsigned)HH;
            const float* yrow = g_y + (((size_t)b * CO + c0 + yc) * HH + (hv ? hh : 0)) * HH;
#pragma unroll
            for (int col = yr; col < 66; col += 64) {
                int ww = wstart + col - 1;
                float v = 0.f;
                if (hv && (unsigned)ww < (unsigned)HH) v = yrow[ww];
                ysm[yc][i3][col] = v;
            }
        }
        __syncthreads();

#pragma unroll
        for (int c = 0; c < 4; c++) {
            u64 z[9];
#pragma unroll
            for (int i3 = 0; i3 < 3; i3++) {
                float2 A  = *(const float2*)&ysm[c][i3][2 * tw];      // y0,y1
                float2 Bv = *(const float2*)&ysm[c][i3][2 * tw + 2];  // y2,y3
                u64 P0 = pk2(A.x,  A.y);
                u64 P1 = pk2(A.y,  Bv.x);
                u64 P2 = pk2(Bv.x, Bv.y);
                z[i3 * 3 + 0] = mul2(P0, kp[i3 * 3 + 0]);
                z[i3 * 3 + 1] = mul2(P1, kp[i3 * 3 + 1]);
                z[i3 * 3 + 2] = mul2(P2, kp[i3 * 3 + 2]);
            }
#pragma unroll
            for (int oi = 0; oi < 16; oi++) {
                const u64* wp = &wsm[c][to * 16 + oi][0];
                ulonglong2 w01 = *(const ulonglong2*)(wp + 0);
                ulonglong2 w23 = *(const ulonglong2*)(wp + 2);
                ulonglong2 w45 = *(const ulonglong2*)(wp + 4);
                ulonglong2 w67 = *(const ulonglong2*)(wp + 6);
                u64 w8 = wp[8];
                u64 s_ = acc[oi];
                s_ = fma2(w01.x, z[0], s_);
                s_ = fma2(w01.y, z[1], s_);
                s_ = fma2(w23.x, z[2], s_);
                s_ = fma2(w23.y, z[3], s_);
                s_ = fma2(w45.x, z[4], s_);
                s_ = fma2(w45.y, z[5], s_);
                s_ = fma2(w67.x, z[6], s_);
                s_ = fma2(w67.y, z[7], s_);
                s_ = fma2(w8,    z[8], s_);
                acc[oi] = s_;
            }
        }
    }

#pragma unroll
    for (int oi = 0; oi < 16; oi++) {
        int o = to * 16 + oi;
        float bias = __ldg(b2 + o);
        float e0, e1; unpk2(acc[oi], e0, e1);
        float2 v = make_float2(e0 + bias, e1 + bias);
        *(float2*)&out[(((size_t)b * CO + o) * HH + h) * HH + w] = v;
    }
}

// ---------------------------------------------------------------------------
extern "C" void kernel_launch(void* const* d_in, const int* in_sizes, int n_in,
                              void* d_out, int out_size)
{
    (void)in_sizes; (void)n_in; (void)out_size;
    const float* x     = (const float*)d_in[0];
    const float* guide = (const float*)d_in[1];
    const float* w1    = (const float*)d_in[2];
    const float* b1    = (const float*)d_in[3];
    const float* w2    = (const float*)d_in[4];
    const float* b2    = (const float*)d_in[5];
    float* out = (float*)d_out;

    stage1_kernel<0><<<dim3(64, 2, NB), 256>>>(x, w1, b1);
    stage1_kernel<1><<<dim3(64, 2, NB), 256>>>(x, w1, b1);
    kmap_kernel<<<dim3(8, 8, NB), 256>>>(guide);
    stage2_kernel<<<dim3(2, HH, NB), 256>>>(w2, b2, out);
}

// round 3
// speedup vs baseline: 1.0003x; 1.0003x over previous
#include <cuda_runtime.h>

#define NB   4
#define CIN  256
#define CO   128
#define HIN  64
#define HH   128

typedef unsigned long long u64;

// ---- packed fp32x2 helpers (sm_100+ dual-rate fp32) ----
__device__ __forceinline__ u64 pk2(float lo, float hi) {
    u64 r;
    asm("mov.b64 %0, {%1, %2};" : "=l"(r)
        : "r"(__float_as_uint(lo)), "r"(__float_as_uint(hi)));
    return r;
}
__device__ __forceinline__ void unpk2(u64 v, float& lo, float& hi) {
    unsigned int a, b;
    asm("mov.b64 {%0, %1}, %2;" : "=r"(a), "=r"(b) : "l"(v));
    lo = __uint_as_float(a); hi = __uint_as_float(b);
}
__device__ __forceinline__ u64 fma2(u64 a, u64 b, u64 c) {
    u64 d;
    asm("fma.rn.f32x2 %0, %1, %2, %3;" : "=l"(d) : "l"(a), "l"(b), "l"(c));
    return d;
}
__device__ __forceinline__ u64 mul2(u64 a, u64 b) {
    u64 d;
    asm("mul.rn.f32x2 %0, %1, %2;" : "=l"(d) : "l"(a), "l"(b));
    return d;
}

// Scratch (device globals: allocation is banned)
__device__ float g_y[(size_t)NB * CO * HH * HH];   // stage-1 output, NCHW
__device__ float g_k[(size_t)NB * 9 * HH * HH];    // PAC gaussian weights [b][tap][h][w]

// ---------------------------------------------------------------------------
// Stage 1: ConvTranspose2d(256->128, k=4, s=2, p=1) as 4 parity classes.
// Class (p,q): out(2a+p, 2bb+q) is a 2x2 conv over x. Block = (b,p,a);
// 256 threads, each owns 16(co) x 2(bb). Packed f32x2 over the bb pair;
// weights stored DUPLICATED in smem so one LDS.128 feeds two FFMA2s.
// ---------------------------------------------------------------------------
template <int Q>
__global__ __launch_bounds__(256, 2) void stage1_kernel(
    const float* __restrict__ x, const float* __restrict__ w1,
    const float* __restrict__ b1)
{
    const int a   = blockIdx.x;          // 0..63
    const int p   = blockIdx.y;          // 0..1
    const int b   = blockIdx.z;          // 0..3
    const int tid = threadIdx.x;
    const int to  = tid >> 5;            // 0..7  -> co base = to*16
    const int tw  = tid & 31;            // bb pair = 2*tw, 2*tw+1

    const int khb = p ? 0 : 1;
    const int kwb = Q ? 0 : 1;
    const int r0  = a + (p ? 1 : 0);     // x row for s=0; s=1 uses r0-1

    __shared__ u64   wsm[8][128][4];     // dup pairs, taps (s,t): (0,0)(0,1)(1,0)(1,1)
    __shared__ float xsm[8][2][68];      // [ci][s][iw+1], padded row

    u64 acc[16];
#pragma unroll
    for (int i = 0; i < 16; i++) acc[i] = 0ull;

    const float* xb = x + (size_t)b * CIN * HIN * HIN;
    const int lci  = tid >> 5;           // ci this thread fills in x slab
    const int lane = tid & 31;

    for (int c0 = 0; c0 < CIN; c0 += 8) {
        __syncthreads();
        // weights: 8 ci x 128 co, 4 taps each, duplicated lanes (shift/mask only)
#pragma unroll 4
        for (int i = tid; i < 8 * 128; i += 256) {
            int ci = i >> 7, co = i & 127;
            const float* wp = w1 + ((size_t)(c0 + ci) * CO + co) * 16;
            float v0 = __ldg(wp + khb * 4 + kwb);
            float v1 = __ldg(wp + khb * 4 + kwb + 2);
            float v2 = __ldg(wp + (khb + 2) * 4 + kwb);
            float v3 = __ldg(wp + (khb + 2) * 4 + kwb + 2);
            wsm[ci][co][0] = pk2(v0, v0);
            wsm[ci][co][1] = pk2(v1, v1);
            wsm[ci][co][2] = pk2(v2, v2);
            wsm[ci][co][3] = pk2(v3, v3);
        }
        // x slab: thread group (32 lanes) per ci, no div/mod
#pragma unroll
        for (int s = 0; s < 2; s++) {
            int ih = r0 - s;
            bool hv = (unsigned)ih < (unsigned)HIN;
            const float* xr = xb + ((size_t)(c0 + lci) * HIN + (hv ? ih : 0)) * HIN;
#pragma unroll
            for (int col = lane; col < 66; col += 32) {
                int iw = col - 1;
                float v = 0.f;
                if (hv && (unsigned)iw < (unsigned)HIN) v = __ldg(xr + iw);
                xsm[lci][s][col] = v;
            }
        }
        __syncthreads();

#pragma unroll
        for (int ci = 0; ci < 8; ci++) {
            float2 A0 = *(const float2*)&xsm[ci][0][2 * tw];
            float2 B0 = *(const float2*)&xsm[ci][0][2 * tw + 2];
            float2 A1 = *(const float2*)&xsm[ci][1][2 * tw];
            float2 B1 = *(const float2*)&xsm[ci][1][2 * tw + 2];
            u64 PA0, PB0, PA1, PB1;   // PA=(xv[M0],xv[M0+1]) PB=(xv[M0-1],xv[M0])
            if (Q) {                  // M0 = 2
                PA0 = pk2(B0.x, B0.y); PB0 = pk2(A0.y, B0.x);
                PA1 = pk2(B1.x, B1.y); PB1 = pk2(A1.y, B1.x);
            } else {                  // M0 = 1
                PA0 = pk2(A0.y, B0.x); PB0 = pk2(A0.x, A0.y);
                PA1 = pk2(A1.y, B1.x); PB1 = pk2(A1.x, A1.y);
            }
#pragma unroll
            for (int oi = 0; oi < 16; oi++) {
                const u64* wp = &wsm[ci][to * 16 + oi][0];
                ulonglong2 wa = *(const ulonglong2*)(wp + 0);
                ulonglong2 wb = *(const ulonglong2*)(wp + 2);
                u64 s_ = acc[oi];
                s_ = fma2(wa.x, PA0, s_);
                s_ = fma2(wa.y, PB0, s_);
                s_ = fma2(wb.x, PA1, s_);
                s_ = fma2(wb.y, PB1, s_);
                acc[oi] = s_;
            }
        }
    }

    const int oh = 2 * a + p;
#pragma unroll
    for (int oi = 0; oi < 16; oi++) {
        int co = to * 16 + oi;
        float bias = __ldg(b1 + co);
        float e0, e1; unpk2(acc[oi], e0, e1);
        size_t base = (((size_t)b * CO + co) * HH + oh) * HH;
        g_y[base + 4 * tw + Q]     = e0 + bias;
        g_y[base + 4 * tw + 2 + Q] = e1 + bias;
    }
}

// ---------------------------------------------------------------------------
// Stage 2a: PAC gaussian kernel map (unchanged; ~30us, not the bottleneck)
// ---------------------------------------------------------------------------
__global__ __launch_bounds__(256) void kmap_kernel(const float* __restrict__ guide)
{
    const int b  = blockIdx.z;
    const int h0 = blockIdx.y * 16, w0 = blockIdx.x * 16;
    const int tx = threadIdx.x & 15, ty = threadIdx.x >> 4;

    __shared__ float sm[18][18];
    float acc[9];
#pragma unroll
    for (int t = 0; t < 9; t++) acc[t] = 0.f;

    for (int c = 0; c < CO; c++) {
        __syncthreads();
        for (int i = threadIdx.x; i < 18 * 18; i += 256) {
            int r = i / 18, col = i % 18;
            int h = h0 + r - 1, w = w0 + col - 1;
            float v = 0.f;
            if ((unsigned)h < (unsigned)HH && (unsigned)w < (unsigned)HH)
                v = __ldg(guide + (((size_t)b * CO + c) * HH + h) * HH + w);
            sm[r][col] = v;
        }
        __syncthreads();
        float g0 = sm[ty + 1][tx + 1];
#pragma unroll
        for (int i3 = 0; i3 < 3; i3++)
#pragma unroll
            for (int j3 = 0; j3 < 3; j3++) {
                float d = sm[ty + i3][tx + j3] - g0;
                acc[i3 * 3 + j3] = fmaf(d, d, acc[i3 * 3 + j3]);
            }
    }

    int h = h0 + ty, w = w0 + tx;
#pragma unroll
    for (int t = 0; t < 9; t++)
        g_k[(((size_t)b * 9 + t) * HH + h) * HH + w] = __expf(-0.5f * acc[t]);
}

// ---------------------------------------------------------------------------
// Stage 2b: PAC transposed conv. wk[o,c,t] = w2[c,o,8-t].
// Block = (b, h, 64-px strip); 256 threads, 16(o) x 2(px) micro-tile.
// Packed f32x2 over the px pair; weights duplicated in smem (LDS.128 pairs),
// per-pixel gaussian taps packed once into registers.
// ---------------------------------------------------------------------------
__global__ __launch_bounds__(256, 2) void stage2_kernel(
    const float* __restrict__ w2, const float* __restrict__ b2,
    float* __restrict__ out)
{
    const int wstart = blockIdx.x * 64;
    const int h      = blockIdx.y;
    const int b      = blockIdx.z;
    const int tid    = threadIdx.x;
    const int to     = tid >> 5;         // 0..7 -> o base = to*16
    const int tw     = tid & 31;         // px pair = wstart + 2*tw + {0,1}
    const int w      = wstart + 2 * tw;

    __shared__ u64   wsm[4][128][10];    // dup pairs, 9 taps + pad (80B stride)
    __shared__ float ysm[4][3][68];      // padded rows

    u64 kp[9];
#pragma unroll
    for (int t = 0; t < 9; t++) {
        size_t kb = (((size_t)b * 9 + t) * HH + h) * HH + w;
        kp[t] = pk2(g_k[kb], g_k[kb + 1]);
    }

    u64 acc[16];
#pragma unroll
    for (int i = 0; i < 16; i++) acc[i] = 0ull;

    const int lo_o   = tid & 127;        // weight-fill: o index
    const int lo_c2  = (tid >> 7) * 2;   // weight-fill: c pair base
    const int yc     = tid >> 6;         // y-fill: c index (0..3)
    const int yr     = tid & 63;         // y-fill: lane within c

    for (int c0 = 0; c0 < CO; c0 += 4) {
        __syncthreads();
        // weights (flip folded): wsm[c][o][t] = dup(w2[(c0+c)*CO*9 + o*9 + 8-t])
#pragma unroll
        for (int cc = 0; cc < 2; cc++) {
            int c = lo_c2 + cc;
            const float* wp = w2 + ((size_t)(c0 + c) * CO + lo_o) * 9;
#pragma unroll
            for (int t = 0; t < 9; t++) {
                float v = __ldg(wp + 8 - t);
                wsm[c][lo_o][t] = pk2(v, v);
            }
        }
        // y slab: 4c x 3 rows x 66 cols (no div/mod)
#pragma unroll
        for (int i3 = 0; i3 < 3; i3++) {
            int hh = h + i3 - 1;
            bool hv = (unsigned)hh < (unsigned)HH;
            const float* yrow = g_y + (((size_t)b * CO + c0 + yc) * HH + (hv ? hh : 0)) * HH;
#pragma unroll
            for (int col = yr; col < 66; col += 64) {
                int ww = wstart + col - 1;
                float v = 0.f;
                if (hv && (unsigned)ww < (unsigned)HH) v = yrow[ww];
                ysm[yc][i3][col] = v;
            }
        }
        __syncthreads();

#pragma unroll
        for (int c = 0; c < 4; c++) {
            u64 z[9];
#pragma unroll
            for (int i3 = 0; i3 < 3; i3++) {
                float2 A  = *(const float2*)&ysm[c][i3][2 * tw];      // y0,y1
                float2 Bv = *(const float2*)&ysm[c][i3][2 * tw + 2];  // y2,y3
                u64 P0 = pk2(A.x,  A.y);
                u64 P1 = pk2(A.y,  Bv.x);
                u64 P2 = pk2(Bv.x, Bv.y);
                z[i3 * 3 + 0] = mul2(P0, kp[i3 * 3 + 0]);
                z[i3 * 3 + 1] = mul2(P1, kp[i3 * 3 + 1]);
                z[i3 * 3 + 2] = mul2(P2, kp[i3 * 3 + 2]);
            }
#pragma unroll
            for (int oi = 0; oi < 16; oi++) {
                const u64* wp = &wsm[c][to * 16 + oi][0];
                ulonglong2 w01 = *(const ulonglong2*)(wp + 0);
                ulonglong2 w23 = *(const ulonglong2*)(wp + 2);
                ulonglong2 w45 = *(const ulonglong2*)(wp + 4);
                ulonglong2 w67 = *(const ulonglong2*)(wp + 6);
                u64 w8 = wp[8];
                u64 s_ = acc[oi];
                s_ = fma2(w01.x, z[0], s_);
                s_ = fma2(w01.y, z[1], s_);
                s_ = fma2(w23.x, z[2], s_);
                s_ = fma2(w23.y, z[3], s_);
                s_ = fma2(w45.x, z[4], s_);
                s_ = fma2(w45.y, z[5], s_);
                s_ = fma2(w67.x, z[6], s_);
                s_ = fma2(w67.y, z[7], s_);
                s_ = fma2(w8,    z[8], s_);
                acc[oi] = s_;
            }
        }
    }

#pragma unroll
    for (int oi = 0; oi < 16; oi++) {
        int o = to * 16 + oi;
        float bias = __ldg(b2 + o);
        float e0, e1; unpk2(acc[oi], e0, e1);
        float2 v = make_float2(e0 + bias, e1 + bias);
        *(float2*)&out[(((size_t)b * CO + o) * HH + h) * HH + w] = v;
    }
}

// ---------------------------------------------------------------------------
extern "C" void kernel_launch(void* const* d_in, const int* in_sizes, int n_in,
                              void* d_out, int out_size)
{
    (void)in_sizes; (void)n_in; (void)out_size;
    const float* x     = (const float*)d_in[0];
    const float* guide = (const float*)d_in[1];
    const float* w1    = (const float*)d_in[2];
    const float* b1    = (const float*)d_in[3];
    const float* w2    = (const float*)d_in[4];
    const float* b2    = (const float*)d_in[5];
    float* out = (float*)d_out;

    stage1_kernel<0><<<dim3(64, 2, NB), 256>>>(x, w1, b1);
    stage1_kernel<1><<<dim3(64, 2, NB), 256>>>(x, w1, b1);
    kmap_kernel<<<dim3(8, 8, NB), 256>>>(guide);
    stage2_kernel<<<dim3(2, HH, NB), 256>>>(w2, b2, out);
}

// round 10
// speedup vs baseline: 3.0556x; 3.0548x over previous
#include <cuda_runtime.h>
#include <cuda_bf16.h>
#include <cstdint>

typedef unsigned int u32;

#define NB 4
#define CIN 256
#define CO 128
#define HIN 64
#define HH 128

// fragment-ordered weights (prepped once per launch) + intermediates
__device__ __align__(16) u32 g_W1H[4*64*8*32*4];   // [cls][k16][mg][lane][reg]
__device__ __align__(16) u32 g_W1L[4*64*8*32*4];
__device__ __align__(16) u32 g_W2H[9*8*8*32*4];    // [tap][k16][mg][lane][reg]
__device__ __align__(16) u32 g_W2L[9*8*8*32*4];
__device__ float g_y[(size_t)NB*CO*HH*HH];
__device__ float g_k[(size_t)NB*9*HH*HH];

__device__ __forceinline__ void splitpack(float v0, float v1, u32& hp, u32& lp){
    __nv_bfloat16 h0=__float2bfloat16(v0), h1=__float2bfloat16(v1);
    __nv_bfloat16 l0=__float2bfloat16(v0-__bfloat162float(h0));
    __nv_bfloat16 l1=__float2bfloat16(v1-__bfloat162float(h1));
    hp=(u32)__bfloat16_as_ushort(h0)|((u32)__bfloat16_as_ushort(h1)<<16);
    lp=(u32)__bfloat16_as_ushort(l0)|((u32)__bfloat16_as_ushort(l1)<<16);
}
__device__ __forceinline__ void mma16816(float* d, const uint4& a, u32 b0, u32 b1){
    asm volatile("mma.sync.aligned.m16n8k16.row.col.f32.bf16.bf16.f32 "
        "{%0,%1,%2,%3},{%4,%5,%6,%7},{%8,%9},{%0,%1,%2,%3};"
        : "+f"(d[0]),"+f"(d[1]),"+f"(d[2]),"+f"(d[3])
        : "r"(a.x),"r"(a.y),"r"(a.z),"r"(a.w),"r"(b0),"r"(b1));
}

// ------------- weight prep: write A fragments in register order -------------
__global__ void prep1(const float* __restrict__ w1){
    int idx = blockIdx.x*256 + threadIdx.x;              // 262144
    int reg=idx&3, lane=(idx>>2)&31, mg=(idx>>7)&7, k16=(idx>>10)&63, cls=(idx>>16)&3;
    int row = mg*16 + (lane>>2) + (reg&1)*8;             // co
    int kb  = k16*16 + (lane&3)*2 + (reg>>1)*8;
    int pp=cls>>1, qq=cls&1;
    float v[2];
#pragma unroll
    for(int kk=0;kk<2;kk++){
        int k=kb+kk, ci=k>>2, s=(k>>1)&1, t=k&1;
        int kh=(pp?0:1)+2*s, kw=(qq?0:1)+2*t;
        v[kk]=__ldg(w1 + (((size_t)ci*CO+row)*4+kh)*4+kw);
    }
    u32 hp,lp; splitpack(v[0],v[1],hp,lp);
    g_W1H[idx]=hp; g_W1L[idx]=lp;
}
__global__ void prep2(const float* __restrict__ w2){
    int idx = blockIdx.x*256 + threadIdx.x;              // 73728
    int reg=idx&3, lane=(idx>>2)&31, mg=(idx>>7)&7, k16=(idx>>10)&7, ti=idx>>13;
    int row = mg*16 + (lane>>2) + (reg&1)*8;             // o
    int cb  = k16*16 + (lane&3)*2 + (reg>>1)*8;
    float v[2];
#pragma unroll
    for(int kk=0;kk<2;kk++)
        v[kk]=__ldg(w2 + ((size_t)(cb+kk)*CO+row)*9 + 8-ti);   // flip folded
    u32 hp,lp; splitpack(v[0],v[1],hp,lp);
    g_W2H[idx]=hp; g_W2L[idx]=lp;
}

// ------------- PAC gaussian kernel map -------------
__global__ __launch_bounds__(256) void kmap_kernel(const float* __restrict__ guide){
    const int b=blockIdx.z, h0=blockIdx.y*16, w0=blockIdx.x*16;
    const int tx=threadIdx.x&15, ty=threadIdx.x>>4;
    __shared__ float sm[18][18];
    float acc[9];
#pragma unroll
    for(int t=0;t<9;t++) acc[t]=0.f;
    for(int c=0;c<CO;c++){
        __syncthreads();
        for(int i=threadIdx.x;i<18*18;i+=256){
            int r=i/18, col=i%18, h=h0+r-1, w=w0+col-1;
            float v=0.f;
            if((unsigned)h<HH && (unsigned)w<HH)
                v=__ldg(guide+(((size_t)b*CO+c)*HH+h)*HH+w);
            sm[r][col]=v;
        }
        __syncthreads();
        float g0=sm[ty+1][tx+1];
#pragma unroll
        for(int i3=0;i3<3;i3++)
#pragma unroll
        for(int j3=0;j3<3;j3++){
            float d=sm[ty+i3][tx+j3]-g0;
            acc[i3*3+j3]=fmaf(d,d,acc[i3*3+j3]);
        }
    }
    int h=h0+ty, w=w0+tx;
#pragma unroll
    for(int t=0;t<9;t++)
        g_k[(((size_t)b*9+t)*HH+h)*HH+w]=__expf(-0.5f*acc[t]);
}

// ------------- stage 1: 4 parity-class implicit GEMMs, M=128 N=128 K=1024 ----
__global__ __launch_bounds__(256) void s1mma(
    const float* __restrict__ x, const float* __restrict__ b1)
{
    __shared__ u32 BH[4][16][64], BL[4][16][64];   // [k16 step][n8 group][frag words]
    const int tid=threadIdx.x, wid=tid>>5, lane=tid&31;
    const int a0=blockIdx.x*2, cls=blockIdx.y, b=blockIdx.z;
    const int pp=cls>>1, qq=cls&1;
    const int warpM=wid>>2, warpN=wid&3;
    const int bkc=wid>>1, bng0=(wid&1)*8, n8=lane>>2, q=lane&3;

    float acc[4][4][4];
#pragma unroll
    for(int i=0;i<4;i++)
#pragma unroll
    for(int j=0;j<4;j++)
#pragma unroll
    for(int r=0;r<4;r++) acc[i][j][r]=0.f;

    for(int cc=0;cc<16;cc++){
        // ---- build B tile (im2col, fragment order) ----
#pragma unroll
        for(int gi=0;gi<8;gi++){
            int ng=bng0+gi, n=ng*8+n8;
            int ai=n>>6, bb=n&63;
#pragma unroll
            for(int j=0;j<2;j++){
                int kg = cc*64 + bkc*16 + q*2 + j*8;    // even; pair (kg, kg+1)
                int ci = kg>>2, s=(kg>>1)&1;
                int rowx = a0+ai+pp-s;
                bool rv = (unsigned)rowx < HIN;
                const float* bp = x + (((size_t)b*CIN+ci)*HIN + (rv?rowx:0))*HIN;
                int c0 = bb+qq;
                float v0 = (rv && c0<HIN) ? __ldg(bp+c0)   : 0.f;  // t=0
                float v1 = (rv && c0>0  ) ? __ldg(bp+c0-1) : 0.f;  // t=1
                u32 hp,lp; splitpack(v0,v1,hp,lp);
                BH[bkc][ng][lane*2+j]=hp; BL[bkc][ng][lane*2+j]=lp;
            }
        }
        __syncthreads();
        // ---- compute ----
#pragma unroll
        for(int ks=0;ks<4;ks++){
            u32 base = ((((u32)cls*64 + cc*4+ks)*8 + warpM*4)*32 + lane)*4;
            uint4 ah[4], al[4];
#pragma unroll
            for(int mi=0;mi<4;mi++){
                ah[mi]=*(const uint4*)&g_W1H[base+mi*128];
                al[mi]=*(const uint4*)&g_W1L[base+mi*128];
            }
#pragma unroll
            for(int nj=0;nj<4;nj++){
                int ng=warpN*4+nj;
                u32 bh0=BH[ks][ng][lane*2], bh1=BH[ks][ng][lane*2+1];
                u32 bl0=BL[ks][ng][lane*2], bl1=BL[ks][ng][lane*2+1];
#pragma unroll
                for(int mi=0;mi<4;mi++){
                    mma16816(acc[mi][nj], ah[mi], bh0, bh1);
                    mma16816(acc[mi][nj], ah[mi], bl0, bl1);
                    mma16816(acc[mi][nj], al[mi], bh0, bh1);
                }
            }
        }
        __syncthreads();
    }
    // ---- epilogue: bias + scatter to NCHW y ----
#pragma unroll
    for(int mi=0;mi<4;mi++){
        int cob = warpM*64+mi*16+(lane>>2);
        float bias0=__ldg(b1+cob), bias1=__ldg(b1+cob+8);
#pragma unroll
        for(int nj=0;nj<4;nj++)
#pragma unroll
        for(int r=0;r<4;r++){
            int co = cob + (r>>1)*8;
            int n  = warpN*32+nj*8+(lane&3)*2+(r&1);
            int ai=n>>6, bb=n&63;
            int oh=2*(a0+ai)+pp, ow=2*bb+qq;
            g_y[(((size_t)b*CO+co)*HH+oh)*HH+ow] = acc[mi][nj][r] + ((r>>1)?bias1:bias0);
        }
    }
}

// ------------- stage 2: PAC conv as GEMM, M=128 N=128 K=1152 (gauss in B) ----
__global__ __launch_bounds__(256) void s2mma(
    const float* __restrict__ b2, float* __restrict__ out)
{
    __shared__ u32 BH[4][16][64], BL[4][16][64];
    const int tid=threadIdx.x, wid=tid>>5, lane=tid&31;
    const int h=blockIdx.x, b=blockIdx.y;
    const int warpM=wid>>2, warpN=wid&3;
    const int bkc=wid>>1, bng0=(wid&1)*8, n8=lane>>2, q=lane&3;

    float acc[4][4][4];
#pragma unroll
    for(int i=0;i<4;i++)
#pragma unroll
    for(int j=0;j<4;j++)
#pragma unroll
    for(int r=0;r<4;r++) acc[i][j][r]=0.f;

    for(int cc=0;cc<18;cc++){
        int ti=cc>>1, chalf=(cc&1)*64;
        int dh=ti/3-1, dw=ti-(ti/3)*3-1;
        int hh=h+dh;
        bool hv=(unsigned)hh<HH;
        // ---- build B: y[c][hh][n+dw] * k[ti][n], fragment order ----
#pragma unroll
        for(int gi=0;gi<8;gi++){
            int ng=bng0+gi, n=ng*8+n8;
            int col=n+dw;
            bool cv=hv && (unsigned)col<HH;
            float kv=__ldg(&g_k[(((size_t)b*9+ti)*HH+h)*HH+n]);
#pragma unroll
            for(int j=0;j<2;j++){
                int c=chalf+bkc*16+q*2+j*8;              // pair (c, c+1)
                const float* yp=&g_y[(((size_t)b*CO+c)*HH+(hv?hh:0))*HH+(cv?col:0)];
                float v0 = cv ? __ldg(yp)*kv              : 0.f;
                float v1 = cv ? __ldg(yp+(size_t)HH*HH)*kv : 0.f;
                u32 hp,lp; splitpack(v0,v1,hp,lp);
                BH[bkc][ng][lane*2+j]=hp; BL[bkc][ng][lane*2+j]=lp;
            }
        }
        __syncthreads();
        // ---- compute ----
#pragma unroll
        for(int ks=0;ks<4;ks++){
            u32 base = ((((u32)ti*8 + (cc&1)*4+ks)*8 + warpM*4)*32 + lane)*4;
            uint4 ah[4], al[4];
#pragma unroll
            for(int mi=0;mi<4;mi++){
                ah[mi]=*(const uint4*)&g_W2H[base+mi*128];
                al[mi]=*(const uint4*)&g_W2L[base+mi*128];
            }
#pragma unroll
            for(int nj=0;nj<4;nj++){
                int ng=warpN*4+nj;
                u32 bh0=BH[ks][ng][lane*2], bh1=BH[ks][ng][lane*2+1];
                u32 bl0=BL[ks][ng][lane*2], bl1=BL[ks][ng][lane*2+1];
#pragma unroll
                for(int mi=0;mi<4;mi++){
                    mma16816(acc[mi][nj], ah[mi], bh0, bh1);
                    mma16816(acc[mi][nj], ah[mi], bl0, bl1);
                    mma16816(acc[mi][nj], al[mi], bh0, bh1);
                }
            }
        }
        __syncthreads();
    }
    // ---- epilogue ----
#pragma unroll
    for(int mi=0;mi<4;mi++){
        int ob = warpM*64+mi*16+(lane>>2);
        float bias0=__ldg(b2+ob), bias1=__ldg(b2+ob+8);
#pragma unroll
        for(int nj=0;nj<4;nj++)
#pragma unroll
        for(int r=0;r<4;r++){
            int o = ob + (r>>1)*8;
            int n = warpN*32+nj*8+(lane&3)*2+(r&1);
            out[(((size_t)b*CO+o)*HH+h)*HH+n] = acc[mi][nj][r] + ((r>>1)?bias1:bias0);
        }
    }
}

// ---------------------------------------------------------------------------
extern "C" void kernel_launch(void* const* d_in, const int* in_sizes, int n_in,
                              void* d_out, int out_size)
{
    (void)in_sizes;(void)n_in;(void)out_size;
    const float* x     =(const float*)d_in[0];
    const float* guide =(const float*)d_in[1];
    const float* w1    =(const float*)d_in[2];
    const float* b1    =(const float*)d_in[3];
    const float* w2    =(const float*)d_in[4];
    const float* b2    =(const float*)d_in[5];
    float* out=(float*)d_out;

    prep1<<<1024,256>>>(w1);
    prep2<<<288,256>>>(w2);
    kmap_kernel<<<dim3(8,8,NB),256>>>(guide);
    s1mma<<<dim3(32,4,NB),256>>>(x,b1);
    s2mma<<<dim3(HH,NB),256>>>(b2,out);
}